// round 13
// baseline (speedup 1.0000x reference)
#include <cuda_runtime.h>
#include <cstddef>

#define IMG_H 512
#define IMG_W 512
#define IMGF  (IMG_H * IMG_W * 3)
#define TILE_W 64
#define TILE_H 32
#define NP_TOT 1024
#define OUTF_PER_B (NP_TOT * 768)
#define RST   204                 // floats per smem tile row (200 used + pad)
#define NROW  34                  // TILE_H + 2 halo
#define FILL4 (NROW * 51)         // float4 stores to fill tile = 1734

__constant__ float c_w[81];   // [ky][kx][ci][co] HWIO
__constant__ float c_b_unused[1];

// Output-linear permuted pos_emb with bias folded in (batch-independent), 3 MB.
__device__ float d_pe_perm[OUTF_PER_B];

// ---- prep: vectorized permute (1 float4/thread), bias folded ----
__global__ __launch_bounds__(256)
void pe_permute_kernel(const float* __restrict__ pos_emb,
                       const float* __restrict__ bias)
{
    const int j4 = blockIdx.x * 256 + threadIdx.x;     // < 196608
    const int np  = j4 / 192;
    const int rm4 = j4 - np * 192;
    const int r   = rm4 / 12;                          // row in patch
    const int k4  = rm4 - r * 12;                      // float4 within 48-float row
    const int gh  = ((np >> 5) << 4) + r;
    const int fc  = k4 / 3;                            // fine col within patch
    const int sub = k4 - fc * 3;
    const int nf  = (gh >> 2) * 128 + ((np & 31) << 2) + fc;
    const int src4 = nf * 12 + (gh & 3) * 3 + sub;

    float4 v = ((const float4*)pos_emb)[src4];
    const float bb[3] = { bias[0], bias[1], bias[2] };
    const int c0 = k4 % 3;
    v.x += bb[c0];
    v.y += bb[(c0 + 1) % 3];
    v.z += bb[(c0 + 2) % 3];
    v.w += bb[c0];
    ((float4*)d_pe_perm)[j4] = v;
}

__device__ __forceinline__ void load_row_s(const float* __restrict__ srow,
                                           bool zl, bool zr, float f[20])
{
#pragma unroll
    for (int j = 0; j < 5; j++) {
        float4 v = *(const float4*)(srow + 4 * j);
        f[4*j+0] = v.x; f[4*j+1] = v.y; f[4*j+2] = v.z; f[4*j+3] = v.w;
    }
    if (zl) { f[1]  = 0.f; f[2]  = 0.f; f[3]  = 0.f; }
    if (zr) { f[16] = 0.f; f[17] = 0.f; f[18] = 0.f; }
}

__device__ __forceinline__ void apply_row(const float f[20], float acc[12], const int wrow)
{
#pragma unroll
    for (int x = 0; x < 4; x++) {
#pragma unroll
        for (int dx = 0; dx < 3; dx++) {
#pragma unroll
            for (int ci = 0; ci < 3; ci++) {
                const float v = f[3*(x + dx) + ci + 1];
                const int wb = ((wrow*3 + dx)*3 + ci)*3;
                acc[x*3 + 0] += v * c_w[wb + 0];
                acc[x*3 + 1] += v * c_w[wb + 1];
                acc[x*3 + 2] += v * c_w[wb + 2];
            }
        }
    }
}

__global__ __launch_bounds__(256, 4)
void patchenc_v7_kernel(const float* __restrict__ X,
                        float* __restrict__ out)
{
    // Tile buffer (27744 B), reused as output staging (24576 B) after conv.
    __shared__ float s[NROW * RST];
    float4* const sout4 = (float4*)s;

    const int b  = blockIdx.z;
    const int h0 = blockIdx.y * TILE_H;
    const int w0 = blockIdx.x * TILE_W;
    const float* __restrict__ Xb = X + (size_t)b * IMGF;

    // ---- phase 0: coalesced tile fill (rows h0-1 .. h0+32) ----
    // smem(row, col) = X[3*((h0-1+row)*512 + w0) - 4 + col], zero outside image.
    {
        const int gbase = 3 * ((h0 - 1) * IMG_W + w0) - 4;
        for (int p = threadIdx.x; p < FILL4; p += 256) {
            const int row = p / 51;
            const int j   = p - row * 51;
            const int gh  = h0 - 1 + row;
            const int g   = gbase + row * (3 * IMG_W) + 4 * j;
            float4 v = make_float4(0.f, 0.f, 0.f, 0.f);
            if ((unsigned)gh < (unsigned)IMG_H && g >= 0 && g + 3 < IMGF)
                v = *(const float4*)(Xb + g);
            *(float4*)&s[row * RST + 4 * j] = v;
        }
    }
    __syncthreads();

    // ---- phase 1: conv from smem windows ----
    const int txq = threadIdx.x & 15;
    const int tyq = threadIdx.x >> 4;
    const int gh0 = h0 + 2 * tyq;

    const bool zl = (w0 == 0) && (txq == 0);
    const bool zr = (w0 == IMG_W - TILE_W) && (txq == 15);

    float acc0[12], acc1[12];
#pragma unroll
    for (int i = 0; i < 12; i++) { acc0[i] = 0.f; acc1[i] = 0.f; }

    const float* rbase = &s[(2 * tyq) * RST + 12 * txq];
    float f[20];

    load_row_s(rbase + 0 * RST, zl, zr, f);
    apply_row(f, acc0, 0);
    load_row_s(rbase + 1 * RST, zl, zr, f);
    apply_row(f, acc0, 1);
    apply_row(f, acc1, 0);
    load_row_s(rbase + 2 * RST, zl, zr, f);
    apply_row(f, acc0, 2);
    apply_row(f, acc1, 1);
    load_row_s(rbase + 3 * RST, zl, zr, f);
    apply_row(f, acc1, 2);

    __syncthreads();   // all tile reads done before smem reuse

    // ---- phase 2: stage into output-ordered smem ----
    const int band = tyq >> 3;
    const int pch  = txq >> 2;
#pragma unroll
    for (int k = 0; k < 2; k++) {
        const float* acc = (k == 0) ? acc0 : acc1;
        const int gh = gh0 + k;
        float4* so = &sout4[band * 768 + pch * 192 + (gh & 15) * 12 + (txq & 3) * 3];
        so[0] = make_float4(acc[0], acc[1],  acc[2],  acc[3]);
        so[1] = make_float4(acc[4], acc[5],  acc[6],  acc[7]);
        so[2] = make_float4(acc[8], acc[9],  acc[10], acc[11]);
    }

    __syncthreads();

    // ---- phase 3: linear copy-out fused with linear PE(+bias) add ----
    const int npb0 = (h0 >> 4) * 32 + (w0 >> 4);
    const float4* pe4 = (const float4*)d_pe_perm;
    float4* ob = (float4*)out + (size_t)b * (OUTF_PER_B / 4);

#pragma unroll
    for (int k = 0; k < 6; k++) {
        const int v  = threadIdx.x + k * 256;        // 0..1535
        const int bd = (v >= 768) ? 1 : 0;
        const int rm = v - bd * 768;
        const size_t g4 = (size_t)(npb0 + bd * 32) * 192 + rm;
        float4 sv = sout4[v];
        float4 p  = pe4[g4];
        ob[g4] = make_float4(sv.x + p.x, sv.y + p.y, sv.z + p.z, sv.w + p.w);
    }
}

extern "C" void kernel_launch(void* const* d_in, const int* in_sizes, int n_in,
                              void* d_out, int out_size)
{
    const float* X  = (const float*)d_in[0];
    const float* Kw = (const float*)d_in[1];
    const float* Bb = (const float*)d_in[2];
    const float* PE = (const float*)d_in[3];

    cudaMemcpyToSymbolAsync(c_w, Kw, 81 * sizeof(float), 0, cudaMemcpyDeviceToDevice, 0);

    pe_permute_kernel<<<768, 256>>>(PE, Bb);

    dim3 grid(IMG_W / TILE_W, IMG_H / TILE_H, 32);
    patchenc_v7_kernel<<<grid, 256>>>(X, (float*)d_out);
}

// round 15
// speedup vs baseline: 1.4738x; 1.4738x over previous
#include <cuda_runtime.h>
#include <cstddef>

#define IMG_H 512
#define IMG_W 512
#define IMGF  (IMG_H * IMG_W * 3)
#define TILE_W 64
#define TILE_H 32
#define NP_TOT 1024
#define OUTF_PER_B (NP_TOT * 768)

__constant__ float c_w[81];   // [ky][kx][ci][co] HWIO

// Output-linear permuted pos_emb with bias folded in (batch-independent), 3 MB.
__device__ float d_pe_perm[OUTF_PER_B];

// ---- prep: vectorized permute (1 float4/thread), bias folded ----
__global__ __launch_bounds__(256)
void pe_permute_kernel(const float* __restrict__ pos_emb,
                       const float* __restrict__ bias)
{
    const int j4 = blockIdx.x * 256 + threadIdx.x;     // < 196608
    const int np  = j4 / 192;
    const int rm4 = j4 - np * 192;
    const int r   = rm4 / 12;
    const int k4  = rm4 - r * 12;
    const int gh  = ((np >> 5) << 4) + r;
    const int fc  = k4 / 3;
    const int sub = k4 - fc * 3;
    const int nf  = (gh >> 2) * 128 + ((np & 31) << 2) + fc;
    const int src4 = nf * 12 + (gh & 3) * 3 + sub;

    float4 v = ((const float4*)pos_emb)[src4];
    const float bb[3] = { bias[0], bias[1], bias[2] };
    const int c0 = k4 % 3;
    v.x += bb[c0];
    v.y += bb[(c0 + 1) % 3];
    v.z += bb[(c0 + 2) % 3];
    v.w += bb[c0];
    ((float4*)d_pe_perm)[j4] = v;
}

// Dense per-thread row load (3 aligned LDG.128) + shuffle halos.
// rq = float4 index of this row's tile start (384*r + 3*w0/4).
__device__ __forceinline__ void load_row_shfl(const float4* __restrict__ X4,
                                              int rq, bool rvalid, int txq,
                                              bool wleft, bool wright,
                                              float f[20])
{
    float4 A = make_float4(0.f,0.f,0.f,0.f);
    float4 B = A, C = A, E = A;
    const bool left  = (txq == 0);
    const bool right = (txq == 15);

    if (rvalid) {
        const int q0 = rq + 3 * txq;
        A = X4[q0];
        B = X4[q0 + 1];
        C = X4[q0 + 2];
        if ((left && wleft) || (right && wright))
            E = X4[left ? (q0 - 1) : (q0 + 3)];
    }

    // halos from neighbor lanes (width-16 segments share a row)
    float L0 = __shfl_up_sync(0xffffffffu, C.y, 1, 16);
    float L1 = __shfl_up_sync(0xffffffffu, C.z, 1, 16);
    float L2 = __shfl_up_sync(0xffffffffu, C.w, 1, 16);
    float R0 = __shfl_down_sync(0xffffffffu, A.x, 1, 16);
    float R1 = __shfl_down_sync(0xffffffffu, A.y, 1, 16);
    float R2 = __shfl_down_sync(0xffffffffu, A.z, 1, 16);
    if (left)  { L0 = E.y; L1 = E.z; L2 = E.w; }   // E==0 at image border
    if (right) { R0 = E.x; R1 = E.y; R2 = E.z; }

    f[1]  = L0;  f[2]  = L1;  f[3]  = L2;
    f[4]  = A.x; f[5]  = A.y; f[6]  = A.z; f[7]  = A.w;
    f[8]  = B.x; f[9]  = B.y; f[10] = B.z; f[11] = B.w;
    f[12] = C.x; f[13] = C.y; f[14] = C.z; f[15] = C.w;
    f[16] = R0;  f[17] = R1;  f[18] = R2;
}

__device__ __forceinline__ void apply_row(const float f[20], float acc[12], const int wrow)
{
#pragma unroll
    for (int x = 0; x < 4; x++) {
#pragma unroll
        for (int dx = 0; dx < 3; dx++) {
#pragma unroll
            for (int ci = 0; ci < 3; ci++) {
                const float v = f[3*(x + dx) + ci + 1];
                const int wb = ((wrow*3 + dx)*3 + ci)*3;
                acc[x*3 + 0] += v * c_w[wb + 0];
                acc[x*3 + 1] += v * c_w[wb + 1];
                acc[x*3 + 2] += v * c_w[wb + 2];
            }
        }
    }
}

__global__ __launch_bounds__(256, 4)
void patchenc_v8_kernel(const float* __restrict__ X,
                        float* __restrict__ out)
{
    __shared__ float4 sout4[1536];   // 24 KB, output-ordered

    const int b  = blockIdx.z;
    const int h0 = blockIdx.y * TILE_H;
    const int w0 = blockIdx.x * TILE_W;
    const float4* __restrict__ X4 = (const float4*)(X + (size_t)b * IMGF);

    const int txq = threadIdx.x & 15;
    const int tyq = threadIdx.x >> 4;
    const int gh0 = h0 + 2 * tyq;

    const bool wleft  = (w0 > 0);
    const bool wright = (w0 + TILE_W < IMG_W);
    const int wq = (3 * w0) >> 2;                 // float4 offset of tile in row

    float acc0[12], acc1[12];
#pragma unroll
    for (int i = 0; i < 12; i++) { acc0[i] = 0.f; acc1[i] = 0.f; }

    float f[20];
    {
        const int r = gh0 - 1;
        load_row_shfl(X4, 384 * r + wq, r >= 0, txq, wleft, wright, f);
        apply_row(f, acc0, 0);
    }
    {
        load_row_shfl(X4, 384 * gh0 + wq, true, txq, wleft, wright, f);
        apply_row(f, acc0, 1);
        apply_row(f, acc1, 0);
    }
    {
        load_row_shfl(X4, 384 * (gh0 + 1) + wq, true, txq, wleft, wright, f);
        apply_row(f, acc0, 2);
        apply_row(f, acc1, 1);
    }
    {
        const int r = gh0 + 2;
        load_row_shfl(X4, 384 * r + wq, r < IMG_H, txq, wleft, wright, f);
        apply_row(f, acc1, 2);
    }

    // ---- stage into output-ordered smem ----
    const int band = tyq >> 3;
    const int pch  = txq >> 2;
#pragma unroll
    for (int k = 0; k < 2; k++) {
        const float* acc = (k == 0) ? acc0 : acc1;
        const int gh = gh0 + k;
        float4* so = &sout4[band * 768 + pch * 192 + (gh & 15) * 12 + (txq & 3) * 3];
        so[0] = make_float4(acc[0], acc[1],  acc[2],  acc[3]);
        so[1] = make_float4(acc[4], acc[5],  acc[6],  acc[7]);
        so[2] = make_float4(acc[8], acc[9],  acc[10], acc[11]);
    }

    __syncthreads();

    // ---- linear copy-out fused with linear PE(+bias) add ----
    const int npb0 = (h0 >> 4) * 32 + (w0 >> 4);
    const float4* pe4 = (const float4*)d_pe_perm;
    float4* ob = (float4*)out + (size_t)b * (OUTF_PER_B / 4);

#pragma unroll
    for (int k = 0; k < 6; k++) {
        const int v  = threadIdx.x + k * 256;        // 0..1535
        const int bd = (v >= 768) ? 1 : 0;
        const int rm = v - bd * 768;
        const size_t g4 = (size_t)(npb0 + bd * 32) * 192 + rm;
        float4 sv = sout4[v];
        float4 p  = pe4[g4];
        ob[g4] = make_float4(sv.x + p.x, sv.y + p.y, sv.z + p.z, sv.w + p.w);
    }
}

extern "C" void kernel_launch(void* const* d_in, const int* in_sizes, int n_in,
                              void* d_out, int out_size)
{
    const float* X  = (const float*)d_in[0];
    const float* Kw = (const float*)d_in[1];
    const float* Bb = (const float*)d_in[2];
    const float* PE = (const float*)d_in[3];

    cudaMemcpyToSymbolAsync(c_w, Kw, 81 * sizeof(float), 0, cudaMemcpyDeviceToDevice, 0);

    pe_permute_kernel<<<768, 256>>>(PE, Bb);

    dim3 grid(IMG_W / TILE_W, IMG_H / TILE_H, 32);
    patchenc_v8_kernel<<<grid, 256>>>(X, (float*)d_out);
}